// round 13
// baseline (speedup 1.0000x reference)
#include <cuda_runtime.h>
#include <cstdint>
#include <math.h>

#define T_FRAMES 1001
#define BATCH    16
#define LSIG     240000
#define HOP      240
#define DIN      301
#define HID      128
#define DOUTN    64
#define NROWS    (T_FRAMES*BATCH)   // 16016
#define FPAD     304                // padded feature row stride (16B aligned)

typedef unsigned long long ull;
typedef unsigned int u32;

// ------------------------- static device scratch -------------------------
__device__ float2 g_tw[1024];                  // twiddles e^{-2pi i k/2048}
__device__ float  g_feat[NROWS * DIN];         // features [row=t*16+b][301]
__device__ float  g_wihT[DIN * 1024];          // transposed input weights [k][g]
__device__ float  g_bias[1024];
__device__ float  g_pre[NROWS * 1024];         // pre-activations [row][1024]
__device__ float2 g_whhP[2 * 64 * 512];        // [d][k2][g] = (W[g][2k2], W[g][2k2+1])
__device__ float  g_hcat[NROWS * 256];         // [row][fwd 0..127 | bwd 128..255]
__device__ float  g_owT[256 * 64];             // out_w transposed [k][o]

// ------------------------------ prep kernel ------------------------------
__global__ void prep_kernel(const float* __restrict__ wihf, const float* __restrict__ whhf,
                            const float* __restrict__ bf,   const float* __restrict__ wihb,
                            const float* __restrict__ whhb, const float* __restrict__ bb,
                            const float* __restrict__ outw)
{
    int tid = blockIdx.x * blockDim.x + threadIdx.x;
    int nth = gridDim.x * blockDim.x;

    for (int k = tid; k < 1024; k += nth) {
        float s, c;
        sincospif((float)k * (1.0f/1024.0f), &s, &c);
        g_tw[k] = make_float2(c, -s);
    }
    for (int i = tid; i < DIN*1024; i += nth) {
        int g = i & 1023, k = i >> 10;
        g_wihT[i] = (g < 512) ? wihf[g*DIN + k] : wihb[(g-512)*DIN + k];
    }
    for (int g = tid; g < 1024; g += nth)
        g_bias[g] = (g < 512) ? bf[g] : bb[g-512];
    for (int i = tid; i < 2*64*512; i += nth) {
        int d = i >> 15;
        int k2 = (i >> 9) & 63;
        int g = i & 511;
        const float* W = d ? whhb : whhf;
        g_whhP[i] = make_float2(W[g*HID + 2*k2], W[g*HID + 2*k2 + 1]);
    }
    for (int i = tid; i < 256*64; i += nth) {
        int o = i & 63, k = i >> 6;
        g_owT[i] = outw[o*256 + k];
    }
}

// ---------------------- STFT (real-packed) + features ---------------------
__device__ __forceinline__ float wsamp(const float* __restrict__ xb, int t, int j)
{
    int q = t*HOP + j - 1024;
    if (q < 0) q = -q;
    else if (q >= LSIG) q = 2*LSIG - 2 - q;
    int jw = j - 544;
    float wv = (jw >= 0 && jw < 960) ? (0.5f - 0.5f*cospif((float)jw * (1.0f/480.0f))) : 0.0f;
    return xb[q] * wv;
}

__global__ __launch_bounds__(256) void stft_kernel(const float* __restrict__ x,
                                                   const float* __restrict__ f0)
{
    __shared__ float2 S[1024];
    int t = blockIdx.x, b = blockIdx.y, tid = threadIdx.x;
    const float* xb = x + b * LSIG;

    // pack even/odd windowed samples into 1024 complex, bit-reversed (10 bit)
    for (int n = tid; n < 1024; n += 256) {
        float v0 = wsamp(xb, t, 2*n);
        float v1 = wsamp(xb, t, 2*n + 1);
        int rev = __brev((unsigned)n) >> 22;
        S[rev] = make_float2(v0, v1);
    }
    __syncthreads();

    // radix-2^2: fused stage pairs (s, s+1) — 4-element group per thread,
    // identical float ops/order as sequential radix-2, half the smem traffic.
    #pragma unroll
    for (int s = 1; s <= 9; s += 2) {
        int h = 1 << (s-1);
        int pos = tid & (h-1);
        int grp = tid >> (s-1);
        int base = (grp << (s+1)) + pos;
        float2 tws = g_tw[pos << (11-s)];
        float2 twa = g_tw[pos << (10-s)];
        float2 twb = g_tw[(pos + h) << (10-s)];
        float2 u0 = S[base], v0 = S[base+h], u1 = S[base+2*h], v1 = S[base+3*h];
        // stage s
        float tr = tws.x*v0.x - tws.y*v0.y, ti = tws.x*v0.y + tws.y*v0.x;
        float2 A0 = make_float2(u0.x+tr, u0.y+ti), A1 = make_float2(u0.x-tr, u0.y-ti);
        tr = tws.x*v1.x - tws.y*v1.y; ti = tws.x*v1.y + tws.y*v1.x;
        float2 B0 = make_float2(u1.x+tr, u1.y+ti), B1 = make_float2(u1.x-tr, u1.y-ti);
        // stage s+1
        tr = twa.x*B0.x - twa.y*B0.y; ti = twa.x*B0.y + twa.y*B0.x;
        S[base]       = make_float2(A0.x+tr, A0.y+ti);
        S[base+2*h]   = make_float2(A0.x-tr, A0.y-ti);
        tr = twb.x*B1.x - twb.y*B1.y; ti = twb.x*B1.y + twb.y*B1.x;
        S[base+h]     = make_float2(A1.x+tr, A1.y+ti);
        S[base+3*h]   = make_float2(A1.x-tr, A1.y-ti);
        __syncthreads();
    }

    // harmonic gather with real-FFT unpack: X[k] = Xe[k] + e^{-i pi k/1024} Xo[k]
    float f0v = f0[b*T_FRAMES + t];
    float f0nz = (f0v > 0.0f) ? f0v : 80.0f;
    int rowbase = (t*BATCH + b) * DIN;
    for (int j = tid; j < 300; j += 256) {
        float m = 0.5f * (float)(j + 1);
        float harm = f0nz * m;
        float r = harm / 11.71875f;
        int k = (int)rintf(r);
        k = min(max(k, 0), 1024);
        float p = 0.0f;
        if (k < 1024) {
            int kr = (1024 - k) & 1023;
            float2 a = S[k];
            float2 zr = S[kr];
            float br = zr.x, bi = -zr.y;
            float xer = 0.5f*(a.x + br), xei = 0.5f*(a.y + bi);
            float dr = a.x - br, di = a.y - bi;
            float xo_r = 0.5f*di, xo_i = -0.5f*dr;
            float sn, cs;
            sincospif((float)k * (1.0f/1024.0f), &sn, &cs);
            float wr = cs, wi = -sn;
            float Xr = xer + wr*xo_r - wi*xo_i;
            float Xi = xei + wr*xo_i + wi*xo_r;
            p = Xr*Xr + Xi*Xi;
        }
        g_feat[rowbase + j] = (logf(p + 1e-8f) + 18.0f) / 23.0f;
    }
    if (tid == 0) g_feat[rowbase + 300] = logf(f0nz);
}

// ---------------------------- input pre-GEMM ------------------------------
__global__ __launch_bounds__(256) void pre_gemm_kernel()
{
    __shared__ float s_feat[16 * FPAD];   // padded rows -> aligned float4 over k
    int t = blockIdx.x;
    int cb = blockIdx.y * 512;
    int tid = threadIdx.x;

    int base = t * 16 * DIN;
    for (int i = tid; i < 16*DIN; i += 256) {
        int row = i / DIN, col = i - row*DIN;
        s_feat[row*FPAD + col] = g_feat[base + i];
    }
    __syncthreads();

    int cl = (tid & 127) * 4 + cb;
    int rh = tid >> 7;
    float4 acc[8];
    float4 bias = *(const float4*)&g_bias[cl];
    #pragma unroll
    for (int r = 0; r < 8; r++) acc[r] = bias;

    const float* fb = s_feat + rh*8*FPAD;
    // k in chunks of 4 (300 = 75*4), accumulation order per output unchanged
    for (int k = 0; k < 300; k += 4) {
        float4 f4[8];
        #pragma unroll
        for (int r = 0; r < 8; r++) f4[r] = *(const float4*)&fb[r*FPAD + k];
        #pragma unroll
        for (int kk = 0; kk < 4; kk++) {
            float4 w = *(const float4*)&g_wihT[(k+kk)*1024 + cl];
            #pragma unroll
            for (int r = 0; r < 8; r++) {
                float f = (kk == 0) ? f4[r].x : (kk == 1) ? f4[r].y : (kk == 2) ? f4[r].z : f4[r].w;
                acc[r].x += f*w.x; acc[r].y += f*w.y; acc[r].z += f*w.z; acc[r].w += f*w.w;
            }
        }
    }
    {   // tail k = 300
        float4 w = *(const float4*)&g_wihT[300*1024 + cl];
        #pragma unroll
        for (int r = 0; r < 8; r++) {
            float f = fb[r*FPAD + 300];
            acc[r].x += f*w.x; acc[r].y += f*w.y; acc[r].z += f*w.z; acc[r].w += f*w.w;
        }
    }
    #pragma unroll
    for (int r = 0; r < 8; r++) {
        int row = t*16 + rh*8 + r;
        *(float4*)&g_pre[row*1024 + cl] = acc[r];
    }
}

// ------------------------------ bi-LSTM ----------------------------------
__device__ __forceinline__ float fsigm(float x) {
    float e = __expf(-fabsf(x));
    float inv = __fdividef(1.0f, 1.0f + e);
    return (x >= 0.0f) ? inv : e * inv;
}
__device__ __forceinline__ float ftanh(float x) {
    float e = __expf(-2.0f * fabsf(x));
    float r = __fdividef(1.0f - e, 1.0f + e);
    return copysignf(r, x);
}
__device__ __forceinline__ ull ffma2(ull a, ull b, ull c) {
    ull d;
    asm("fma.rn.f32x2 %0, %1, %2, %3;" : "=l"(d) : "l"(a), "l"(b), "l"(c));
    return d;
}
__device__ __forceinline__ float2 u2f2(ull a) {
    float2 f;
    asm("mov.b64 {%0, %1}, %2;" : "=f"(f.x), "=f"(f.y) : "l"(a));
    return f;
}
#define CLUSTER_SYNC() do { \
    asm volatile("barrier.cluster.arrive.aligned;" ::: "memory"); \
    asm volatile("barrier.cluster.wait.aligned;"   ::: "memory"); \
} while (0)

// cluster of 2 CTAs per (b, d). Scheme H: rank r owns h rows [64r,64r+64) and
// computes the FULL k=128 dot for its 256 gate rows, 2 threads per row
// (k-halves). Only h crosses CTAs: 256B/step via st.async, shipped the moment
// h is produced (before the hcat STG). Own-k-half threads never wait on the
// peer; peer-k-half threads wait on the parity mbarrier, overlapping the
// DSMEM flight with the local half-dot.
__global__ __launch_bounds__(512, 1) __cluster_dims__(2, 1, 1)
void lstm_kernel()
{
    int cid  = blockIdx.x >> 1;      // 0..31
    int rank = blockIdx.x & 1;       // h-row half owned
    int d = cid >> 4, b = cid & 15;
    int tid = threadIdx.x;
    int u  = tid >> 8;               // k-half this thread computes
    int rl = tid & 255;              // local gate row = q*64 + j
    int q  = rl >> 6;
    int j  = rl & 63;
    int grow = q*128 + rank*64 + j;  // global W row

    ull w2[32];
    {
        const ull* WP = (const ull*)g_whhP + ((size_t)d*64 + 32*u)*512 + grow;
        #pragma unroll
        for (int jj = 0; jj < 32; jj++) w2[jj] = WP[jj*512];
    }

    __shared__ __align__(16) ull   h_own2[32];      // own 64 h
    __shared__ __align__(16) ull   hpeer2[2][32];   // peer 64 h, parity buffers
    __shared__ float part_sh[512];                  // [u*256 + rl]
    __shared__ __align__(8) ull    s_bar[2];        // parity mbarriers

    if (tid < 32) { h_own2[tid] = 0ULL; hpeer2[0][tid] = 0ULL; hpeer2[1][tid] = 0ULL; }
    u32 bar_local   = (u32)__cvta_generic_to_shared(s_bar);
    u32 hpeer_local = (u32)__cvta_generic_to_shared(hpeer2);
    if (tid == 0) {
        asm volatile("mbarrier.init.shared.b64 [%0], 1;" :: "r"(bar_local)     : "memory");
        asm volatile("mbarrier.init.shared.b64 [%0], 1;" :: "r"(bar_local + 8) : "memory");
        asm volatile("mbarrier.arrive.expect_tx.shared.b64 _, [%0], %1;"
                     :: "r"(bar_local),     "r"(256u) : "memory");
        asm volatile("mbarrier.arrive.expect_tx.shared.b64 _, [%0], %1;"
                     :: "r"(bar_local + 8), "r"(256u) : "memory");
    }
    float c_state = 0.0f;
    __syncthreads();
    CLUSTER_SYNC();   // peer barriers armed before any st.async

    u32 hpeer_c, bar_peer_c;
    asm("mapa.shared::cluster.u32 %0, %1, %2;" : "=r"(hpeer_c)   : "r"(hpeer_local), "r"((u32)(rank^1)));
    asm("mapa.shared::cluster.u32 %0, %1, %2;" : "=r"(bar_peer_c): "r"(bar_local),   "r"((u32)(rank^1)));

    const float* preB = g_pre + d*512;
    float* hcatB = g_hcat + d*HID + rank*64;
    int jglob = rank*64 + tid;

    // prologue: deliver h0 = 0 for step 0 to the peer's parity-0 buffer
    if (tid < 64) {
        asm volatile("st.async.shared::cluster.mbarrier::complete_tx::bytes.b32 [%0], %1, [%2];"
                     :: "r"(hpeer_c + (u32)tid*4u), "r"(0u), "r"(bar_peer_c) : "memory");
    }

    float pn0 = 0.f, pn1 = 0.f, pn2 = 0.f, pn3 = 0.f;
    if (tid < 64) {
        int t0 = d ? (T_FRAMES - 1) : 0;
        const float* pr = preB + (size_t)(t0*BATCH + b)*1024 + jglob;
        pn0 = pr[0]; pn1 = pr[128]; pn2 = pr[256]; pn3 = pr[384];
    }

    bool iswait = (u != rank);
    for (int s = 0; s < T_FRAMES; s++) {
        int t = d ? (T_FRAMES - 1 - s) : s;
        int row = t*BATCH + b;
        u32 par = (u32)(s & 1);
        u32 ph  = (u32)((s >> 1) & 1);

        float p0 = pn0, p1 = pn1, p2 = pn2, p3 = pn3;
        if (tid < 64 && s + 1 < T_FRAMES) {
            int tn = d ? (T_FRAMES - 2 - s) : (s + 1);
            const float* pr = preB + (size_t)(tn*BATCH + b)*1024 + jglob;
            pn0 = pr[0]; pn1 = pr[128]; pn2 = pr[256]; pn3 = pr[384];
        }

        if (iswait) {
            asm volatile("{\n\t"
                         ".reg .pred P;\n"
                         "LW%=:\n\t"
                         "mbarrier.try_wait.parity.acquire.cta.shared::cta.b64 P, [%0], %1, 0x989680;\n\t"
                         "@!P bra LW%=;\n\t"
                         "}" :: "r"(bar_local + 8u*par), "r"(ph) : "memory");
            if (rl == 0 && s + 2 < T_FRAMES) {
                asm volatile("mbarrier.arrive.expect_tx.shared.b64 _, [%0], %1;"
                             :: "r"(bar_local + 8u*par), "r"(256u) : "memory");
            }
        }

        const ulonglong2* hh = iswait ? (const ulonglong2*)hpeer2[par]
                                      : (const ulonglong2*)h_own2;
        ull a0 = 0ULL, a1 = 0ULL, a2 = 0ULL, a3 = 0ULL;
        #pragma unroll
        for (int jj = 0; jj < 8; jj++) {
            ulonglong2 hA = hh[2*jj], hB = hh[2*jj+1];
            a0 = ffma2(w2[4*jj+0], hA.x, a0);
            a1 = ffma2(w2[4*jj+1], hA.y, a1);
            a2 = ffma2(w2[4*jj+2], hB.x, a2);
            a3 = ffma2(w2[4*jj+3], hB.y, a3);
        }
        float2 f0v = u2f2(a0), f1v = u2f2(a1), f2v = u2f2(a2), f3v = u2f2(a3);
        part_sh[tid] = ((f0v.x + f0v.y) + (f1v.x + f1v.y))
                     + ((f2v.x + f2v.y) + (f3v.x + f3v.y));
        __syncthreads();

        if (tid < 64) {
            float zi = (part_sh[tid]     + part_sh[256+tid]) + p0;
            float zf = (part_sh[64+tid]  + part_sh[320+tid]) + p1;
            float zg = (part_sh[128+tid] + part_sh[384+tid]) + p2;
            float zo = (part_sh[192+tid] + part_sh[448+tid]) + p3;
            c_state = fsigm(zf)*c_state + fsigm(zi)*ftanh(zg);
            float h = fsigm(zo)*ftanh(c_state);
            if (s + 1 < T_FRAMES) {   // ship h to peer FIRST (critical path)
                asm volatile("st.async.shared::cluster.mbarrier::complete_tx::bytes.b32 [%0], %1, [%2];"
                             :: "r"(hpeer_c + (par^1u)*256u + (u32)tid*4u),
                                "r"(__float_as_uint(h)),
                                "r"(bar_peer_c + 8u*(par^1u)) : "memory");
            }
            ((float*)h_own2)[tid] = h;
            hcatB[(size_t)row*256 + tid] = h;
        }
        __syncthreads();
    }
    CLUSTER_SYNC();
}

// ----------------------- LayerNorm + output GEMM --------------------------
__global__ __launch_bounds__(256) void final_kernel(const float* __restrict__ ln_g,
                                                    const float* __restrict__ ln_b,
                                                    const float* __restrict__ out_b,
                                                    float* __restrict__ out)
{
    __shared__ float sh[16*256];
    __shared__ float s_sum[256], s_sq[256];
    __shared__ float s_mu[16], s_rstd[16];

    int t = blockIdx.x, tid = threadIdx.x;
    for (int i = tid; i < 4096; i += 256) sh[i] = g_hcat[t*4096 + i];
    __syncthreads();

    {
        int row = tid >> 4, seg = tid & 15;
        float sm = 0.f, sq = 0.f;
        const float* p = sh + row*256 + seg*16;
        #pragma unroll
        for (int u = 0; u < 16; u++) { float v = p[u]; sm += v; sq += v*v; }
        s_sum[tid] = sm; s_sq[tid] = sq;
    }
    __syncthreads();
    if (tid < 16) {
        float sm = 0.f, sq = 0.f;
        #pragma unroll
        for (int u = 0; u < 16; u++) { sm += s_sum[tid*16 + u]; sq += s_sq[tid*16 + u]; }
        float mu = sm * (1.0f/256.0f);
        float var = sq * (1.0f/256.0f) - mu*mu;
        s_mu[tid] = mu;
        s_rstd[tid] = rsqrtf(var + 1e-5f);
    }
    __syncthreads();
    for (int i = tid; i < 4096; i += 256) {
        int r = i >> 8, k = i & 255;
        sh[i] = (sh[i] - s_mu[r]) * s_rstd[r] * ln_g[k] + ln_b[k];
    }
    __syncthreads();

    int col = tid & 63, rg = tid >> 6;
    float acc[4];
    float bb = out_b[col];
    #pragma unroll
    for (int r = 0; r < 4; r++) acc[r] = bb;
    for (int k = 0; k < 256; k++) {
        float w = g_owT[k*64 + col];
        #pragma unroll
        for (int r = 0; r < 4; r++) acc[r] += sh[(rg*4 + r)*256 + k] * w;
    }
    #pragma unroll
    for (int r = 0; r < 4; r++) {
        int b = rg*4 + r;
        out[(b*T_FRAMES + t)*DOUTN + col] = acc[r];
    }
}

// ------------------------------ launcher ----------------------------------
extern "C" void kernel_launch(void* const* d_in, const int* in_sizes, int n_in,
                              void* d_out, int out_size)
{
    const float* x     = (const float*)d_in[0];
    const float* f0    = (const float*)d_in[1];
    const float* wihf  = (const float*)d_in[2];
    const float* whhf  = (const float*)d_in[3];
    const float* bf    = (const float*)d_in[4];
    const float* wihb  = (const float*)d_in[5];
    const float* whhb  = (const float*)d_in[6];
    const float* bb    = (const float*)d_in[7];
    const float* lng   = (const float*)d_in[8];
    const float* lnb   = (const float*)d_in[9];
    const float* outw  = (const float*)d_in[10];
    const float* outb  = (const float*)d_in[11];
    float* out = (float*)d_out;

    prep_kernel<<<256, 256>>>(wihf, whhf, bf, wihb, whhb, bb, outw);
    stft_kernel<<<dim3(T_FRAMES, BATCH), 256>>>(x, f0);
    pre_gemm_kernel<<<dim3(T_FRAMES, 2), 256>>>();
    lstm_kernel<<<64, 512>>>();
    final_kernel<<<T_FRAMES, 256>>>(lng, lnb, outb, out);
}

// round 15
// speedup vs baseline: 1.1012x; 1.1012x over previous
#include <cuda_runtime.h>
#include <cstdint>
#include <math.h>

#define T_FRAMES 1001
#define BATCH    16
#define LSIG     240000
#define HOP      240
#define DIN      301
#define HID      128
#define DOUTN    64
#define NROWS    (T_FRAMES*BATCH)   // 16016

typedef unsigned long long ull;
typedef unsigned int u32;

// ------------------------- static device scratch -------------------------
__device__ float2 g_tw[1024];                  // twiddles e^{-2pi i k/2048}
__device__ float  g_feat[NROWS * DIN];         // features [row=t*16+b][301]
__device__ float  g_wihT[DIN * 1024];          // transposed input weights [k][g]
__device__ float  g_bias[1024];
__device__ float  g_pre[NROWS * 1024];         // pre-activations [row][1024]
__device__ float2 g_whhP[2 * 64 * 512];        // [d][k2][g] = (W[g][2k2], W[g][2k2+1])
__device__ float  g_hcat[NROWS * 256];         // [row][fwd 0..127 | bwd 128..255]
__device__ float  g_owT[256 * 64];             // out_w transposed [k][o]

// ------------------------------ prep kernel ------------------------------
__global__ void prep_kernel(const float* __restrict__ wihf, const float* __restrict__ whhf,
                            const float* __restrict__ bf,   const float* __restrict__ wihb,
                            const float* __restrict__ whhb, const float* __restrict__ bb,
                            const float* __restrict__ outw)
{
    int tid = blockIdx.x * blockDim.x + threadIdx.x;
    int nth = gridDim.x * blockDim.x;

    for (int k = tid; k < 1024; k += nth) {
        float s, c;
        sincospif((float)k * (1.0f/1024.0f), &s, &c);
        g_tw[k] = make_float2(c, -s);
    }
    for (int i = tid; i < DIN*1024; i += nth) {
        int g = i & 1023, k = i >> 10;
        g_wihT[i] = (g < 512) ? wihf[g*DIN + k] : wihb[(g-512)*DIN + k];
    }
    for (int g = tid; g < 1024; g += nth)
        g_bias[g] = (g < 512) ? bf[g] : bb[g-512];
    for (int i = tid; i < 2*64*512; i += nth) {
        int d = i >> 15;
        int k2 = (i >> 9) & 63;
        int g = i & 511;
        const float* W = d ? whhb : whhf;
        g_whhP[i] = make_float2(W[g*HID + 2*k2], W[g*HID + 2*k2 + 1]);
    }
    for (int i = tid; i < 256*64; i += nth) {
        int o = i & 63, k = i >> 6;
        g_owT[i] = outw[o*256 + k];
    }
}

// ---------------------- STFT (real-packed) + features ---------------------
__device__ __forceinline__ float wsamp(const float* __restrict__ xb, int t, int j)
{
    int q = t*HOP + j - 1024;
    if (q < 0) q = -q;
    else if (q >= LSIG) q = 2*LSIG - 2 - q;
    int jw = j - 544;
    float wv = (jw >= 0 && jw < 960) ? (0.5f - 0.5f*cospif((float)jw * (1.0f/480.0f))) : 0.0f;
    return xb[q] * wv;
}

__global__ __launch_bounds__(256) void stft_kernel(const float* __restrict__ x,
                                                   const float* __restrict__ f0)
{
    __shared__ float2 S[1024];
    int t = blockIdx.x, b = blockIdx.y, tid = threadIdx.x;
    const float* xb = x + b * LSIG;

    for (int n = tid; n < 1024; n += 256) {
        float v0 = wsamp(xb, t, 2*n);
        float v1 = wsamp(xb, t, 2*n + 1);
        int rev = __brev((unsigned)n) >> 22;
        S[rev] = make_float2(v0, v1);
    }
    __syncthreads();

    #pragma unroll
    for (int s = 1; s <= 10; s++) {
        int half = 1 << (s-1);
        for (int idx = tid; idx < 512; idx += 256) {
            int pos = idx & (half - 1);
            int grp = idx >> (s-1);
            int i0 = (grp << s) + pos;
            int i1 = i0 + half;
            float2 tw = g_tw[pos << (11 - s)];
            float2 u = S[i0], v = S[i1];
            float tr = tw.x*v.x - tw.y*v.y;
            float ti = tw.x*v.y + tw.y*v.x;
            S[i0] = make_float2(u.x + tr, u.y + ti);
            S[i1] = make_float2(u.x - tr, u.y - ti);
        }
        __syncthreads();
    }

    float f0v = f0[b*T_FRAMES + t];
    float f0nz = (f0v > 0.0f) ? f0v : 80.0f;
    int rowbase = (t*BATCH + b) * DIN;
    for (int j = tid; j < 300; j += 256) {
        float m = 0.5f * (float)(j + 1);
        float harm = f0nz * m;
        float r = harm / 11.71875f;
        int k = (int)rintf(r);
        k = min(max(k, 0), 1024);
        float p = 0.0f;
        if (k < 1024) {
            int kr = (1024 - k) & 1023;
            float2 a = S[k];
            float2 zr = S[kr];
            float br = zr.x, bi = -zr.y;
            float xer = 0.5f*(a.x + br), xei = 0.5f*(a.y + bi);
            float dr = a.x - br, di = a.y - bi;
            float xo_r = 0.5f*di, xo_i = -0.5f*dr;
            float sn, cs;
            sincospif((float)k * (1.0f/1024.0f), &sn, &cs);
            float wr = cs, wi = -sn;
            float Xr = xer + wr*xo_r - wi*xo_i;
            float Xi = xei + wr*xo_i + wi*xo_r;
            p = Xr*Xr + Xi*Xi;
        }
        g_feat[rowbase + j] = (logf(p + 1e-8f) + 18.0f) / 23.0f;
    }
    if (tid == 0) g_feat[rowbase + 300] = logf(f0nz);
}

// ---------------------------- input pre-GEMM ------------------------------
__global__ __launch_bounds__(256) void pre_gemm_kernel()
{
    __shared__ float s_feat[16 * DIN];
    int t = blockIdx.x;
    int cb = blockIdx.y * 512;
    int tid = threadIdx.x;

    int base = t * 16 * DIN;
    for (int i = tid; i < 16*DIN; i += 256) s_feat[i] = g_feat[base + i];
    __syncthreads();

    int cl = (tid & 127) * 4 + cb;
    int rh = tid >> 7;
    float4 acc[8];
    float4 bias = *(const float4*)&g_bias[cl];
    #pragma unroll
    for (int r = 0; r < 8; r++) acc[r] = bias;

    const float* fb = s_feat + rh*8*DIN;
    for (int k = 0; k < DIN; k++) {
        float4 w = *(const float4*)&g_wihT[k*1024 + cl];
        #pragma unroll
        for (int r = 0; r < 8; r++) {
            float f = fb[r*DIN + k];
            acc[r].x += f*w.x; acc[r].y += f*w.y; acc[r].z += f*w.z; acc[r].w += f*w.w;
        }
    }
    #pragma unroll
    for (int r = 0; r < 8; r++) {
        int row = t*16 + rh*8 + r;
        *(float4*)&g_pre[row*1024 + cl] = acc[r];
    }
}

// ------------------------------ bi-LSTM ----------------------------------
__device__ __forceinline__ float fsigm(float x) {
    float e = __expf(-fabsf(x));
    float inv = __fdividef(1.0f, 1.0f + e);
    return (x >= 0.0f) ? inv : e * inv;
}
__device__ __forceinline__ float ftanh(float x) {
    float e = __expf(-2.0f * fabsf(x));
    float r = __fdividef(1.0f - e, 1.0f + e);
    return copysignf(r, x);
}
__device__ __forceinline__ ull ffma2(ull a, ull b, ull c) {
    ull d;
    asm("fma.rn.f32x2 %0, %1, %2, %3;" : "=l"(d) : "l"(a), "l"(b), "l"(c));
    return d;
}
__device__ __forceinline__ float2 u2f2(ull a) {
    float2 f;
    asm("mov.b64 {%0, %1}, %2;" : "=f"(f.x), "=f"(f.y) : "l"(a));
    return f;
}
#define CLUSTER_SYNC() do { \
    asm volatile("barrier.cluster.arrive.aligned;" ::: "memory"); \
    asm volatile("barrier.cluster.wait.aligned;"   ::: "memory"); \
} while (0)

// cluster of 4 CTAs per (b, d). Rank r owns h rows [32r, 32r+32) and computes
// the FULL k=128 dot for its 128 gate rows with 4 threads/row (k-quarters,
// 16 packed-f32x2 weight regs each). Only h crosses CTAs: each CTA's 32 h
// floats go to 3 peers via coalesced st.async (128B/peer); each parity
// mbarrier expects 3*128 = 384B. hbuf[par][src_rank][32] is uniform for all
// k-quarter threads: own-rank slot written locally, peer slots by st.async.
__global__ __launch_bounds__(512, 1) __cluster_dims__(4, 1, 1)
void lstm_kernel()
{
    int cid  = blockIdx.x >> 2;      // 0..31
    int rank = blockIdx.x & 3;       // h-row quarter owned
    int d = cid >> 4, b = cid & 15;
    int tid = threadIdx.x;
    int u  = tid >> 7;               // k-quarter this thread computes (0..3)
    int rl = tid & 127;              // local gate row = q*32 + j
    int q  = rl >> 5;                // gate (i,f,g,o)
    int j  = rl & 31;                // row within this CTA's quarter
    int grow = q*128 + rank*32 + j;  // global W row

    // 32 weights (k in [32u, 32u+32)) as 16 packed f32x2 registers
    ull w2[16];
    {
        const ull* WP = (const ull*)g_whhP + ((size_t)d*64 + 16*u)*512 + grow;
        #pragma unroll
        for (int jj = 0; jj < 16; jj++) w2[jj] = WP[jj*512];
    }

    __shared__ __align__(16) float hbuf[2][4][32];  // [parity][src rank][row]
    __shared__ float part_sh[512];                  // [u*128 + q*32 + j]
    __shared__ __align__(8) ull s_bar[2];           // parity mbarriers

    if (tid < 256) ((float*)hbuf)[tid] = 0.0f;
    u32 bar_local  = (u32)__cvta_generic_to_shared(s_bar);
    u32 hbuf_local = (u32)__cvta_generic_to_shared(hbuf);
    if (tid == 0) {
        asm volatile("mbarrier.init.shared.b64 [%0], 1;" :: "r"(bar_local)     : "memory");
        asm volatile("mbarrier.init.shared.b64 [%0], 1;" :: "r"(bar_local + 8) : "memory");
        // arm steps 0 and 1: 3 peers x 128B each
        asm volatile("mbarrier.arrive.expect_tx.shared.b64 _, [%0], %1;"
                     :: "r"(bar_local),     "r"(384u) : "memory");
        asm volatile("mbarrier.arrive.expect_tx.shared.b64 _, [%0], %1;"
                     :: "r"(bar_local + 8), "r"(384u) : "memory");
    }
    float c_state = 0.0f;
    __syncthreads();
    CLUSTER_SYNC();   // all ranks' barriers armed before any st.async

    // cluster-mapped addresses of every rank's hbuf / bars
    u32 hbuf_all[4], bar_all[4];
    #pragma unroll
    for (int pr = 0; pr < 4; pr++) {
        asm("mapa.shared::cluster.u32 %0, %1, %2;" : "=r"(hbuf_all[pr]) : "r"(hbuf_local), "r"((u32)pr));
        asm("mapa.shared::cluster.u32 %0, %1, %2;" : "=r"(bar_all[pr])  : "r"(bar_local),  "r"((u32)pr));
    }

    const float* preB = g_pre + d*512;
    float* hcatB = g_hcat + d*HID + rank*32;
    int jglob = rank*32 + tid;       // gate threads (tid<32): global h row

    // prologue: deliver h0 = 0 for step 0 (parity 0) to all 3 peers
    if (tid < 32) {
        u32 doff = (u32)rank*128u + (u32)tid*4u;   // [0][rank][tid]
        #pragma unroll
        for (int pr = 0; pr < 4; pr++) if (pr != rank) {
            asm volatile("st.async.shared::cluster.mbarrier::complete_tx::bytes.b32 [%0], %1, [%2];"
                         :: "r"(hbuf_all[pr] + doff), "r"(0u), "r"(bar_all[pr]) : "memory");
        }
    }

    // prefetch pre-activations for step 0 (gate threads only)
    float pn0 = 0.f, pn1 = 0.f, pn2 = 0.f, pn3 = 0.f;
    if (tid < 32) {
        int t0 = d ? (T_FRAMES - 1) : 0;
        const float* pr = preB + (size_t)(t0*BATCH + b)*1024 + jglob;
        pn0 = pr[0]; pn1 = pr[128]; pn2 = pr[256]; pn3 = pr[384];
    }

    bool iswait = (u != rank);                       // needs peer h
    int rearm_tid = (rank == 0) ? 128 : 0;           // first wait-quarter thread
    for (int s = 0; s < T_FRAMES; s++) {
        int t = d ? (T_FRAMES - 1 - s) : s;
        int row = t*BATCH + b;
        u32 par = (u32)(s & 1);
        u32 ph  = (u32)((s >> 1) & 1);

        float p0 = pn0, p1 = pn1, p2 = pn2, p3 = pn3;
        if (tid < 32 && s + 1 < T_FRAMES) {
            int tn = d ? (T_FRAMES - 2 - s) : (s + 1);
            const float* pr = preB + (size_t)(tn*BATCH + b)*1024 + jglob;
            pn0 = pr[0]; pn1 = pr[128]; pn2 = pr[256]; pn3 = pr[384];
        }

        // wait-quarter threads block until all 3 peer h chunks arrive
        if (iswait) {
            asm volatile("{\n\t"
                         ".reg .pred P;\n"
                         "LW%=:\n\t"
                         "mbarrier.try_wait.parity.acquire.cta.shared::cta.b64 P, [%0], %1, 0x989680;\n\t"
                         "@!P bra LW%=;\n\t"
                         "}" :: "r"(bar_local + 8u*par), "r"(ph) : "memory");
            if (tid == rearm_tid && s + 2 < T_FRAMES) {
                asm volatile("mbarrier.arrive.expect_tx.shared.b64 _, [%0], %1;"
                             :: "r"(bar_local + 8u*par), "r"(384u) : "memory");
            }
        }

        // partial over this thread's k-quarter (32 h values): 16 packed FFMA2
        const ulonglong2* hh = (const ulonglong2*)hbuf[par][u];
        ull a0 = 0ULL, a1 = 0ULL, a2 = 0ULL, a3 = 0ULL;
        #pragma unroll
        for (int jj = 0; jj < 4; jj++) {
            ulonglong2 hA = hh[2*jj], hB = hh[2*jj+1];
            a0 = ffma2(w2[4*jj+0], hA.x, a0);
            a1 = ffma2(w2[4*jj+1], hA.y, a1);
            a2 = ffma2(w2[4*jj+2], hB.x, a2);
            a3 = ffma2(w2[4*jj+3], hB.y, a3);
        }
        float2 f0v = u2f2(a0), f1v = u2f2(a1), f2v = u2f2(a2), f3v = u2f2(a3);
        part_sh[tid] = ((f0v.x + f0v.y) + (f1v.x + f1v.y))
                     + ((f2v.x + f2v.y) + (f3v.x + f3v.y));
        __syncthreads();

        if (tid < 32) {   // one gate thread per own h row
            // fixed order: ((u0+u1)+(u2+u3)) + pre
            float zi = ((part_sh[tid]    + part_sh[128+tid]) + (part_sh[256+tid] + part_sh[384+tid])) + p0;
            float zf = ((part_sh[32+tid] + part_sh[160+tid]) + (part_sh[288+tid] + part_sh[416+tid])) + p1;
            float zg = ((part_sh[64+tid] + part_sh[192+tid]) + (part_sh[320+tid] + part_sh[448+tid])) + p2;
            float zo = ((part_sh[96+tid] + part_sh[224+tid]) + (part_sh[352+tid] + part_sh[480+tid])) + p3;
            c_state = fsigm(zf)*c_state + fsigm(zi)*ftanh(zg);
            float h = fsigm(zo)*ftanh(c_state);
            hbuf[par^1][rank][tid] = h;             // local slot for own-quarter dot
            hcatB[(size_t)row*256 + tid] = h;
            if (s + 1 < T_FRAMES) {                 // ship h to all 3 peers
                u32 v = __float_as_uint(h);
                u32 doff = (par^1u)*512u + (u32)rank*128u + (u32)tid*4u;
                #pragma unroll
                for (int pr = 0; pr < 4; pr++) if (pr != rank) {
                    asm volatile("st.async.shared::cluster.mbarrier::complete_tx::bytes.b32 [%0], %1, [%2];"
                                 :: "r"(hbuf_all[pr] + doff), "r"(v),
                                    "r"(bar_all[pr] + 8u*(par^1u)) : "memory");
                }
            }
        }
        __syncthreads();   // hbuf[par^1][rank] visible for next step's own dot
    }
    CLUSTER_SYNC();        // no CTA exits with peer traffic in flight
}

// ----------------------- LayerNorm + output GEMM --------------------------
__global__ __launch_bounds__(256) void final_kernel(const float* __restrict__ ln_g,
                                                    const float* __restrict__ ln_b,
                                                    const float* __restrict__ out_b,
                                                    float* __restrict__ out)
{
    __shared__ float sh[16*256];
    __shared__ float s_sum[256], s_sq[256];
    __shared__ float s_mu[16], s_rstd[16];

    int t = blockIdx.x, tid = threadIdx.x;
    for (int i = tid; i < 4096; i += 256) sh[i] = g_hcat[t*4096 + i];
    __syncthreads();

    {
        int row = tid >> 4, seg = tid & 15;
        float sm = 0.f, sq = 0.f;
        const float* p = sh + row*256 + seg*16;
        #pragma unroll
        for (int u = 0; u < 16; u++) { float v = p[u]; sm += v; sq += v*v; }
        s_sum[tid] = sm; s_sq[tid] = sq;
    }
    __syncthreads();
    if (tid < 16) {
        float sm = 0.f, sq = 0.f;
        #pragma unroll
        for (int u = 0; u < 16; u++) { sm += s_sum[tid*16 + u]; sq += s_sq[tid*16 + u]; }
        float mu = sm * (1.0f/256.0f);
        float var = sq * (1.0f/256.0f) - mu*mu;
        s_mu[tid] = mu;
        s_rstd[tid] = rsqrtf(var + 1e-5f);
    }
    __syncthreads();
    for (int i = tid; i < 4096; i += 256) {
        int r = i >> 8, k = i & 255;
        sh[i] = (sh[i] - s_mu[r]) * s_rstd[r] * ln_g[k] + ln_b[k];
    }
    __syncthreads();

    int col = tid & 63, rg = tid >> 6;
    float acc[4];
    float bb = out_b[col];
    #pragma unroll
    for (int r = 0; r < 4; r++) acc[r] = bb;
    for (int k = 0; k < 256; k++) {
        float w = g_owT[k*64 + col];
        #pragma unroll
        for (int r = 0; r < 4; r++) acc[r] += sh[(rg*4 + r)*256 + k] * w;
    }
    #pragma unroll
    for (int r = 0; r < 4; r++) {
        int b = rg*4 + r;
        out[(b*T_FRAMES + t)*DOUTN + col] = acc[r];
    }
}

// ------------------------------ launcher ----------------------------------
extern "C" void kernel_launch(void* const* d_in, const int* in_sizes, int n_in,
                              void* d_out, int out_size)
{
    const float* x     = (const float*)d_in[0];
    const float* f0    = (const float*)d_in[1];
    const float* wihf  = (const float*)d_in[2];
    const float* whhf  = (const float*)d_in[3];
    const float* bf    = (const float*)d_in[4];
    const float* wihb  = (const float*)d_in[5];
    const float* whhb  = (const float*)d_in[6];
    const float* bb    = (const float*)d_in[7];
    const float* lng   = (const float*)d_in[8];
    const float* lnb   = (const float*)d_in[9];
    const float* outw  = (const float*)d_in[10];
    const float* outb  = (const float*)d_in[11];
    float* out = (float*)d_out;

    prep_kernel<<<256, 256>>>(wihf, whhf, bf, wihb, whhb, bb, outw);
    stft_kernel<<<dim3(T_FRAMES, BATCH), 256>>>(x, f0);
    pre_gemm_kernel<<<dim3(T_FRAMES, 2), 256>>>();
    lstm_kernel<<<128, 512>>>();
    final_kernel<<<T_FRAMES, 256>>>(lng, lnb, outb, out);
}